// round 3
// baseline (speedup 1.0000x reference)
#include <cuda_runtime.h>

#define BS 4
#define NQ 1024
#define NK 1024
#define QD 128
#define VD 128
#define HID 64

#define TQ 8                    // queries per block
#define TK 128                  // keys per score tile
#define RQ 4                    // queries per thread (TQ / 2 q-halves)
#define ATT_THREADS 256
#define ATT_SMEM_FLOATS (TQ*NK + HID*TK + TQ*HID + HID + TQ)
#define ATT_SMEM_BYTES (ATT_SMEM_FLOATS * 4)

// Scratch (allocation-free rule: __device__ globals)
__device__ float g_q [BS * NQ * HID];   // [b][q][h]
__device__ float g_kT[BS * HID * NK];   // [b][h][k]

__device__ __forceinline__ float tanh_fast(float x) {
    float y;
    asm("tanh.approx.f32 %0, %1;" : "=f"(y) : "f"(x));
    return y;
}

// ---------------------------------------------------------------------------
// Projection kernel: q = queries @ W_q -> g_q,  kT = (keys @ W_k)^T -> g_kT
// ---------------------------------------------------------------------------
#define PR 16
__global__ __launch_bounds__(256) void proj_kernel(
    const float* __restrict__ queries, const float* __restrict__ keys,
    const float* __restrict__ W_q, const float* __restrict__ W_k)
{
    __shared__ float Ws[HID][QD + 4];
    __shared__ float xs[PR][QD];

    int bid   = blockIdx.x;
    int which = bid >> 8;               // 0 = q, 1 = k
    int tile  = bid & 255;
    int b     = tile >> 6;
    int r0    = (tile & 63) * PR;

    const float* X = which ? keys : queries;
    const float* W = which ? W_k  : W_q;
    int t = threadIdx.x;

    for (int idx = t; idx < QD * HID; idx += 256) {
        int d = idx >> 6, h = idx & 63;
        Ws[h][d] = W[idx];
    }
    const float* xbase = X + ((size_t)b * NQ + r0) * QD;
    for (int idx = t; idx < PR * QD; idx += 256)
        xs[idx >> 7][idx & 127] = xbase[idx];
    __syncthreads();

    int h  = t & 63;
    int rg = t >> 6;
    float acc[4] = {0.f, 0.f, 0.f, 0.f};
    #pragma unroll 8
    for (int d = 0; d < QD; d += 4) {
        float4 w4 = *(const float4*)&Ws[h][d];
        #pragma unroll
        for (int i = 0; i < 4; i++) {
            float4 x4 = *(const float4*)&xs[rg + 4 * i][d];
            acc[i] = fmaf(w4.x, x4.x, fmaf(w4.y, x4.y,
                     fmaf(w4.z, x4.z, fmaf(w4.w, x4.w, acc[i]))));
        }
    }

    if (which == 0) {
        #pragma unroll
        for (int i = 0; i < 4; i++)
            g_q[((size_t)b * NQ + r0 + rg + 4 * i) * HID + h] = acc[i];
    } else {
        #pragma unroll
        for (int i = 0; i < 4; i++)
            g_kT[((size_t)b * HID + h) * NK + r0 + rg + 4 * i] = acc[i];
    }
}

// ---------------------------------------------------------------------------
// Fused attention: block = (b, 8-query tile), 256 threads, 3 blocks/SM.
// Score phase: thread (tk = t%128, qh = t/128) computes 4 queries x 1 key col.
// ---------------------------------------------------------------------------
__global__ __launch_bounds__(ATT_THREADS, 3) void att_kernel(
    const float* __restrict__ values, const float* __restrict__ w_v,
    float* __restrict__ out)
{
    extern __shared__ float sm[];
    float* ss   = sm;                       // [TQ][NK]    scores -> exp(scores)
    float* ks   = sm + TQ * NK;             // [HID][TK]   k tile (reused as V tile [64][VD])
    float* qs   = ks + HID * TK;            // [TQ][HID]
    float* wvs  = qs + TQ * HID;            // [HID]
    float* sinv = wvs + HID;                // [TQ]

    int t  = threadIdx.x;
    int b  = blockIdx.y;
    int q0 = blockIdx.x * TQ;
    int tk = t & 127;
    int qh = t >> 7;                        // 0 or 1

    {
        const float* qb = g_q + ((size_t)b * NQ + q0) * HID;
        for (int i = t; i < TQ * HID; i += ATT_THREADS) qs[i] = qb[i];
    }
    if (t < HID) wvs[t] = w_v[t];
    __syncthreads();

    // ---- Pass A: scores -------------------------------------------------
    const float* kTb = g_kT + (size_t)b * HID * NK;
    for (int kt = 0; kt < NK / TK; ++kt) {
        for (int i = t; i < HID * TK; i += ATT_THREADS)
            ks[i] = kTb[(i >> 7) * NK + kt * TK + (i & 127)];
        __syncthreads();

        float acc[RQ];
        #pragma unroll
        for (int qi = 0; qi < RQ; ++qi) acc[qi] = 0.f;

        #pragma unroll 4
        for (int h = 0; h < HID; h += 4) {
            float k0 = ks[(h + 0) * TK + tk];
            float k1 = ks[(h + 1) * TK + tk];
            float k2 = ks[(h + 2) * TK + tk];
            float k3 = ks[(h + 3) * TK + tk];
            float4 w4 = *(const float4*)&wvs[h];
            #pragma unroll
            for (int qi = 0; qi < RQ; ++qi) {
                float4 q4 = *(const float4*)&qs[(qh * RQ + qi) * HID + h];
                float s = acc[qi];
                s = fmaf(w4.x, tanh_fast(q4.x + k0), s);
                s = fmaf(w4.y, tanh_fast(q4.y + k1), s);
                s = fmaf(w4.z, tanh_fast(q4.z + k2), s);
                s = fmaf(w4.w, tanh_fast(q4.w + k3), s);
                acc[qi] = s;
            }
        }
        #pragma unroll
        for (int qi = 0; qi < RQ; ++qi)
            ss[(qh * RQ + qi) * NK + kt * TK + tk] = acc[qi];
        __syncthreads();
    }

    // ---- Pass B: softmax (8 warps, 8 rows -> 1 row/warp) ----------------
    int warp = t >> 5, lane = t & 31;
    if (warp < TQ) {
        float* row = ss + warp * NK;
        float m = -1e30f;
        for (int i = lane; i < NK; i += 32) m = fmaxf(m, row[i]);
        #pragma unroll
        for (int o = 16; o > 0; o >>= 1) m = fmaxf(m, __shfl_xor_sync(0xffffffffu, m, o));
        float sum = 0.f;
        for (int i = lane; i < NK; i += 32) {
            float e = __expf(row[i] - m);
            row[i] = e;
            sum += e;
        }
        #pragma unroll
        for (int o = 16; o > 0; o >>= 1) sum += __shfl_xor_sync(0xffffffffu, sum, o);
        if (lane == 0) sinv[warp] = 1.f / sum;
    }
    __syncthreads();

    // ---- Pass C: out = attn @ V  (thread: column tk, query-half qh) -----
    float* vs = ks;                         // reuse as [64][VD]
    float o[RQ];
    #pragma unroll
    for (int qi = 0; qi < RQ; ++qi) o[qi] = 0.f;

    const float* vb = values + (size_t)b * NK * VD;
    for (int jt = 0; jt < NK / 64; ++jt) {
        __syncthreads();                    // previous tile fully consumed
        for (int i = t; i < 64 * VD; i += ATT_THREADS)
            vs[i] = vb[(size_t)jt * 64 * VD + i];
        __syncthreads();
        #pragma unroll 4
        for (int j = 0; j < 64; j += 4) {
            float v0 = vs[(j + 0) * VD + tk];
            float v1 = vs[(j + 1) * VD + tk];
            float v2 = vs[(j + 2) * VD + tk];
            float v3 = vs[(j + 3) * VD + tk];
            #pragma unroll
            for (int qi = 0; qi < RQ; ++qi) {
                float4 a4 = *(const float4*)&ss[(qh * RQ + qi) * NK + jt * 64 + j];
                float s = o[qi];
                s = fmaf(a4.x, v0, s);
                s = fmaf(a4.y, v1, s);
                s = fmaf(a4.z, v2, s);
                s = fmaf(a4.w, v3, s);
                o[qi] = s;
            }
        }
    }

    float* ob = out + ((size_t)b * NQ + q0) * VD;
    #pragma unroll
    for (int qi = 0; qi < RQ; ++qi)
        ob[(qh * RQ + qi) * VD + tk] = o[qi] * sinv[qh * RQ + qi];
}

// ---------------------------------------------------------------------------
extern "C" void kernel_launch(void* const* d_in, const int* in_sizes, int n_in,
                              void* d_out, int out_size)
{
    const float* queries = (const float*)d_in[0];
    const float* keys    = (const float*)d_in[1];
    const float* values  = (const float*)d_in[2];
    const float* W_q     = (const float*)d_in[3];
    const float* W_k     = (const float*)d_in[4];
    const float* w_v     = (const float*)d_in[5];
    float* out = (float*)d_out;

    cudaFuncSetAttribute(att_kernel, cudaFuncAttributeMaxDynamicSharedMemorySize,
                         ATT_SMEM_BYTES);

    proj_kernel<<<512, 256>>>(queries, keys, W_q, W_k);
    att_kernel<<<dim3(NQ / TQ, BS), ATT_THREADS, ATT_SMEM_BYTES>>>(values, w_v, out);
}

// round 4
// speedup vs baseline: 1.1133x; 1.1133x over previous
#include <cuda_runtime.h>
#include <cuda_fp16.h>

#define BS 4
#define NQ 1024
#define NK 1024
#define QD 128
#define VD 128
#define HID 64
#define NP 32                   // half2 h-pairs (HID/2)

#define TQ 8                    // queries per block
#define TK 128                  // keys per score tile
#define RQ 4                    // queries per thread in pass A
#define ATT_THREADS 256

// smem: ss[TQ*NK] f32 | ksh[NP*TK] u32(half2) | qsh[TQ*NP] u32 | wvs[HID] f32 | sinv[TQ]
#define SS_FLOATS   (TQ * NK)
#define KSH_WORDS   (NP * TK)
#define QSH_WORDS   (TQ * NP)
#define ATT_SMEM_BYTES ((SS_FLOATS + KSH_WORDS + QSH_WORDS + HID + TQ) * 4)

__device__ float g_q [BS * NQ * HID];   // [b][q][h]
__device__ float g_kT[BS * HID * NK];   // [b][h][k]

__device__ __forceinline__ unsigned tanh2(unsigned x) {
    unsigned y;
    asm("tanh.approx.f16x2 %0, %1;" : "=r"(y) : "r"(x));
    return y;
}

// ---------------------------------------------------------------------------
// Projection kernel (unchanged): q -> g_q,  kT -> g_kT
// ---------------------------------------------------------------------------
#define PR 16
__global__ __launch_bounds__(256) void proj_kernel(
    const float* __restrict__ queries, const float* __restrict__ keys,
    const float* __restrict__ W_q, const float* __restrict__ W_k)
{
    __shared__ float Ws[HID][QD + 4];
    __shared__ float xs[PR][QD];

    int bid   = blockIdx.x;
    int which = bid >> 8;
    int tile  = bid & 255;
    int b     = tile >> 6;
    int r0    = (tile & 63) * PR;

    const float* X = which ? keys : queries;
    const float* W = which ? W_k  : W_q;
    int t = threadIdx.x;

    for (int idx = t; idx < QD * HID; idx += 256) {
        int d = idx >> 6, h = idx & 63;
        Ws[h][d] = W[idx];
    }
    const float* xbase = X + ((size_t)b * NQ + r0) * QD;
    for (int idx = t; idx < PR * QD; idx += 256)
        xs[idx >> 7][idx & 127] = xbase[idx];
    __syncthreads();

    int h  = t & 63;
    int rg = t >> 6;
    float acc[4] = {0.f, 0.f, 0.f, 0.f};
    #pragma unroll 8
    for (int d = 0; d < QD; d += 4) {
        float4 w4 = *(const float4*)&Ws[h][d];
        #pragma unroll
        for (int i = 0; i < 4; i++) {
            float4 x4 = *(const float4*)&xs[rg + 4 * i][d];
            acc[i] = fmaf(w4.x, x4.x, fmaf(w4.y, x4.y,
                     fmaf(w4.z, x4.z, fmaf(w4.w, x4.w, acc[i]))));
        }
    }

    if (which == 0) {
        #pragma unroll
        for (int i = 0; i < 4; i++)
            g_q[((size_t)b * NQ + r0 + rg + 4 * i) * HID + h] = acc[i];
    } else {
        #pragma unroll
        for (int i = 0; i < 4; i++)
            g_kT[((size_t)b * HID + h) * NK + r0 + rg + 4 * i] = acc[i];
    }
}

// ---------------------------------------------------------------------------
// Fused attention. Pass A uses half2 q/k + tanh.approx.f16x2, fp32 accumulate.
// ---------------------------------------------------------------------------
__global__ __launch_bounds__(ATT_THREADS, 4) void att_kernel(
    const float* __restrict__ values, const float* __restrict__ w_v,
    float* __restrict__ out)
{
    extern __shared__ float sm[];
    float*    ss   = sm;                                   // [TQ][NK]
    unsigned* ksh  = (unsigned*)(sm + SS_FLOATS);          // [NP][TK] half2
    unsigned* qsh  = ksh + KSH_WORDS;                      // [TQ][NP] half2
    float*    wvs  = (float*)(qsh + QSH_WORDS);            // [HID]
    float*    sinv = wvs + HID;                            // [TQ]
    float*    vs   = (float*)ksh;                          // reuse: [32][VD]

    int t  = threadIdx.x;
    int b  = blockIdx.y;
    int q0 = blockIdx.x * TQ;
    int tk = t & 127;
    int qh = t >> 7;                                       // 0 or 1

    // Stage q (half2-packed over h-pairs) + w_v
    {
        const float* qb = g_q + ((size_t)b * NQ + q0) * HID;
        int e = t;                                         // 256 entries, 1/thread
        int qi = e >> 5, p = e & 31;
        __half2 h2 = __floats2half2_rn(qb[qi * HID + 2 * p], qb[qi * HID + 2 * p + 1]);
        qsh[qi * NP + p] = *(unsigned*)&h2;
    }
    if (t < HID) wvs[t] = w_v[t];
    __syncthreads();

    // ---- Pass A: scores -------------------------------------------------
    const float* kTb = g_kT + (size_t)b * HID * NK;
    for (int kt = 0; kt < NK / TK; ++kt) {
        // stage k tile as half2 pairs: ksh[p][tk]
        for (int e = t; e < NP * TK; e += ATT_THREADS) {
            int p = e >> 7, k = e & 127;
            float lo = kTb[(2 * p)     * NK + kt * TK + k];
            float hi = kTb[(2 * p + 1) * NK + kt * TK + k];
            __half2 h2 = __floats2half2_rn(lo, hi);
            ksh[e] = *(unsigned*)&h2;
        }
        __syncthreads();

        float acc[RQ];
        #pragma unroll
        for (int qi = 0; qi < RQ; ++qi) acc[qi] = 0.f;

        #pragma unroll 2
        for (int p = 0; p < NP; p += 2) {
            unsigned ka = ksh[p * TK + tk];
            unsigned kb = ksh[(p + 1) * TK + tk];
            float4 w4 = *(const float4*)&wvs[2 * p];       // w for h = 2p..2p+3
            #pragma unroll
            for (int qi = 0; qi < RQ; ++qi) {
                uint2 q2 = *(const uint2*)&qsh[(qh * RQ + qi) * NP + p];
                __half2 s0 = __hadd2(*(__half2*)&q2.x, *(__half2*)&ka);
                __half2 s1 = __hadd2(*(__half2*)&q2.y, *(__half2*)&kb);
                unsigned t0 = tanh2(*(unsigned*)&s0);
                unsigned t1 = tanh2(*(unsigned*)&s1);
                float2 f0 = __half22float2(*(__half2*)&t0);
                float2 f1 = __half22float2(*(__half2*)&t1);
                float s = acc[qi];
                s = fmaf(w4.x, f0.x, s);
                s = fmaf(w4.y, f0.y, s);
                s = fmaf(w4.z, f1.x, s);
                s = fmaf(w4.w, f1.y, s);
                acc[qi] = s;
            }
        }
        #pragma unroll
        for (int qi = 0; qi < RQ; ++qi)
            ss[(qh * RQ + qi) * NK + kt * TK + tk] = acc[qi];
        __syncthreads();
    }

    // ---- Pass B: softmax (8 warps, 1 row each) --------------------------
    int warp = t >> 5, lane = t & 31;
    {
        float* row = ss + warp * NK;
        float m = -1e30f;
        for (int i = lane; i < NK; i += 32) m = fmaxf(m, row[i]);
        #pragma unroll
        for (int o = 16; o > 0; o >>= 1) m = fmaxf(m, __shfl_xor_sync(0xffffffffu, m, o));
        float sum = 0.f;
        for (int i = lane; i < NK; i += 32) {
            float e = __expf(row[i] - m);
            row[i] = e;
            sum += e;
        }
        #pragma unroll
        for (int o = 16; o > 0; o >>= 1) sum += __shfl_xor_sync(0xffffffffu, sum, o);
        if (lane == 0) sinv[warp] = 1.f / sum;
    }
    __syncthreads();

    // ---- Pass C: out = attn @ V ----------------------------------------
    // thread -> (query q = warp, col group cg = lane): 4 cols, float4 acc
    int q  = warp;
    int cg = lane;
    float4 o4 = make_float4(0.f, 0.f, 0.f, 0.f);

    const float4* vb4 = (const float4*)(values + (size_t)b * NK * VD);
    float4* vs4 = (float4*)vs;
    for (int jt = 0; jt < NK / 32; ++jt) {
        __syncthreads();
        #pragma unroll
        for (int r = 0; r < 4; ++r)
            vs4[t + 256 * r] = vb4[jt * (32 * VD / 4) + t + 256 * r];
        __syncthreads();
        #pragma unroll 2
        for (int j = 0; j < 32; j += 4) {
            float4 a4 = *(const float4*)&ss[q * NK + jt * 32 + j];   // broadcast
            float4 v0 = vs4[(j + 0) * 32 + cg];
            float4 v1 = vs4[(j + 1) * 32 + cg];
            float4 v2 = vs4[(j + 2) * 32 + cg];
            float4 v3 = vs4[(j + 3) * 32 + cg];
            o4.x = fmaf(a4.x, v0.x, fmaf(a4.y, v1.x, fmaf(a4.z, v2.x, fmaf(a4.w, v3.x, o4.x))));
            o4.y = fmaf(a4.x, v0.y, fmaf(a4.y, v1.y, fmaf(a4.z, v2.y, fmaf(a4.w, v3.y, o4.y))));
            o4.z = fmaf(a4.x, v0.z, fmaf(a4.y, v1.z, fmaf(a4.z, v2.z, fmaf(a4.w, v3.z, o4.z))));
            o4.w = fmaf(a4.x, v0.w, fmaf(a4.y, v1.w, fmaf(a4.z, v2.w, fmaf(a4.w, v3.w, o4.w))));
        }
    }

    float si = sinv[q];
    o4.x *= si; o4.y *= si; o4.z *= si; o4.w *= si;
    *(float4*)&out[((size_t)b * NQ + q0 + q) * VD + cg * 4] = o4;
}

// ---------------------------------------------------------------------------
extern "C" void kernel_launch(void* const* d_in, const int* in_sizes, int n_in,
                              void* d_out, int out_size)
{
    const float* queries = (const float*)d_in[0];
    const float* keys    = (const float*)d_in[1];
    const float* values  = (const float*)d_in[2];
    const float* W_q     = (const float*)d_in[3];
    const float* W_k     = (const float*)d_in[4];
    const float* w_v     = (const float*)d_in[5];
    float* out = (float*)d_out;

    cudaFuncSetAttribute(att_kernel, cudaFuncAttributeMaxDynamicSharedMemorySize,
                         ATT_SMEM_BYTES);

    proj_kernel<<<512, 256>>>(queries, keys, W_q, W_k);
    att_kernel<<<dim3(NQ / TQ, BS), ATT_THREADS, ATT_SMEM_BYTES>>>(values, w_v, out);
}